// round 7
// baseline (speedup 1.0000x reference)
#include <cuda_runtime.h>
#include <cstdint>

// ---------------- problem constants ----------------
#define NTOK   32768
#define OUT_FIBER  ((size_t)NTOK * 512)
#define OUT_CONN   (OUT_FIBER + (size_t)NTOK * 1024)
#define OUT_GEN    (OUT_CONN + (size_t)NTOK * 8)

typedef unsigned long long u64;

// Layout: off(row) = row*144 + ((row>>3)<<4)   (16B-aligned everywhere)
// Buffer = 4640 B; per matrix two buffers U,V; matrix 1 offset by MATB+16 so the
// inter-matrix granule delta is 581 mod 8 = 5 (odd -> mm_rr conflict-free,
// mm_ck splat windows overlap only 1 of 4 granules).
#define BUFB   4640
#define MATB   (2 * BUFB)              // 9280
#define SMEMB  (2 * MATB + 16)         // 18576 -> 12 one-warp blocks/SM

// ---------------- packed fp32x2 / smem helpers ----------------
__device__ __forceinline__ u64 pk2(float lo, float hi) {
    u64 r; asm("mov.b64 %0,{%1,%2};" : "=l"(r) : "f"(lo), "f"(hi)); return r;
}
__device__ __forceinline__ void upk2(u64 v, float &lo, float &hi) {
    asm("mov.b64 {%0,%1},%2;" : "=f"(lo), "=f"(hi) : "l"(v));
}
__device__ __forceinline__ u64 ffma2(u64 a, u64 b, u64 c) {
    u64 d; asm("fma.rn.f32x2 %0,%1,%2,%3;" : "=l"(d) : "l"(a), "l"(b), "l"(c)); return d;
}
__device__ __forceinline__ void lds4f(uint32_t a, float &x, float &y, float &z, float &w) {
    asm volatile("ld.shared.v4.f32 {%0,%1,%2,%3},[%4];"
                 : "=f"(x), "=f"(y), "=f"(z), "=f"(w) : "r"(a));
}
__device__ __forceinline__ void lds2l(uint32_t a, u64 &p, u64 &q) {
    asm volatile("ld.shared.v2.u64 {%0,%1},[%2];" : "=l"(p), "=l"(q) : "r"(a));
}
__device__ __forceinline__ void sts4f(uint32_t a, float x, float y, float z, float w) {
    asm volatile("st.shared.v4.f32 [%0],{%1,%2,%3,%4};"
                 :: "r"(a), "f"(x), "f"(y), "f"(z), "f"(w));
}
__device__ __forceinline__ void sts2l(uint32_t a, u64 p, u64 q) {
    asm volatile("st.shared.v2.u64 [%0],{%1,%2};" :: "r"(a), "l"(p), "l"(q));
}

// ---------------- mm_rr: acc += P^T Q over k=0..31 ----------------
// P = buf + it*32 (splat), Q = buf + jq*32 (pair).
__device__ __forceinline__ void mm_rr(uint32_t P, uint32_t Q, u64 acc[8][4]) {
    #pragma unroll 1
    for (int kb = 0; kb < 4; kb++) {
        const uint32_t Pb = P + kb * 1168;
        const uint32_t Qb = Q + kb * 1168;
        #pragma unroll
        for (int kk = 0; kk < 8; kk++) {
            float p0,p1,p2,p3,p4,p5,p6,p7;
            lds4f(Pb + kk * 144,      p0, p1, p2, p3);
            lds4f(Pb + kk * 144 + 16, p4, p5, p6, p7);
            u64 q0, q1, q2, q3;
            lds2l(Qb + kk * 144,      q0, q1);
            lds2l(Qb + kk * 144 + 16, q2, q3);
            float ps[8] = {p0,p1,p2,p3,p4,p5,p6,p7};
            #pragma unroll
            for (int r = 0; r < 8; r++) {
                u64 s = pk2(ps[r], ps[r]);
                acc[r][0] = ffma2(s, q0, acc[r][0]);
                acc[r][1] = ffma2(s, q1, acc[r][1]);
                acc[r][2] = ffma2(s, q2, acc[r][2]);
                acc[r][3] = ffma2(s, q3, acc[r][3]);
            }
        }
    }
}

// ---------------- mm_ck: acc += P Q over k=0..31 ----------------
// P = buf + it*1168 (rows 8it.., k-chunk-major reads), Q = buf + jq*32 (pair).
__device__ __forceinline__ void mm_ck(uint32_t P, uint32_t Q, u64 acc[8][4]) {
    #pragma unroll 1
    for (int kb = 0; kb < 8; kb++) {
        float p[8][4];
        #pragma unroll
        for (int r = 0; r < 8; r++)
            lds4f(P + r * 144 + kb * 16, p[r][0], p[r][1], p[r][2], p[r][3]);
        const uint32_t Qb = Q + kb * 576 + ((kb >> 1) << 4);
        #pragma unroll
        for (int kk = 0; kk < 4; kk++) {
            u64 q0, q1, q2, q3;
            lds2l(Qb + kk * 144,      q0, q1);
            lds2l(Qb + kk * 144 + 16, q2, q3);
            #pragma unroll
            for (int r = 0; r < 8; r++) {
                u64 s = pk2(p[r][kk], p[r][kk]);
                acc[r][0] = ffma2(s, q0, acc[r][0]);
                acc[r][1] = ffma2(s, q1, acc[r][1]);
                acc[r][2] = ffma2(s, q2, acc[r][2]);
                acc[r][3] = ffma2(s, q3, acc[r][3]);
            }
        }
    }
}

__device__ __forceinline__ void zacc(u64 acc[8][4]) {
    #pragma unroll
    for (int r = 0; r < 8; r++)
        #pragma unroll
        for (int c = 0; c < 4; c++) acc[r][c] = 0ull;
}

__device__ __forceinline__ u64 dpair(int ondiag, int r, int c, float v) {
    float dl = (ondiag && r == 2 * c    ) ? v : 0.0f;
    float dh = (ondiag && r == 2 * c + 1) ? v : 0.0f;
    return pk2(dl, dh);
}

// own-tile store (rows 8it+r), base tb = buf + it*1168 + jq*32
__device__ __forceinline__ void st_own(uint32_t tb, u64 v[8][4]) {
    #pragma unroll
    for (int r = 0; r < 8; r++) {
        sts2l(tb + r * 144,      v[r][0], v[r][1]);
        sts2l(tb + r * 144 + 16, v[r][2], v[r][3]);
    }
}
// mirrored (transposed) tile store, base mb = buf + jq*1168 + it*32
__device__ __forceinline__ void st_mirror(uint32_t mb, u64 v[8][4]) {
    #pragma unroll
    for (int c = 0; c < 4; c++) {
        float lo[8], hi[8];
        #pragma unroll
        for (int r = 0; r < 8; r++) upk2(v[r][c], lo[r], hi[r]);
        const uint32_t a0 = mb + (2 * c) * 144;
        sts4f(a0,             lo[0], lo[1], lo[2], lo[3]);
        sts4f(a0 + 16,        lo[4], lo[5], lo[6], lo[7]);
        sts4f(a0 + 144,       hi[0], hi[1], hi[2], hi[3]);
        sts4f(a0 + 144 + 16,  hi[4], hi[5], hi[6], hi[7]);
    }
}

// ---------------- kernel: 1 warp, 2 matrices (16 lanes each) ----------------
__global__ __launch_bounds__(32) void fiber_bundle_kernel(
    const int*   __restrict__ tokens,
    const float* __restrict__ base_w,
    const float* __restrict__ fiber_w,
    const float* __restrict__ conn_w,
    const float* __restrict__ gen,
    float*       __restrict__ out)
{
    __shared__ __align__(128) char smraw[SMEMB];
    const uint32_t S = (uint32_t)__cvta_generic_to_shared(smraw);

    const int lane = threadIdx.x;
    const int m    = lane >> 4;
    const int t    = lane & 15;
    const int it   = t >> 2;                 // row-tile 0..3
    const int jq   = t & 3;                  // col-tile 0..3

    const uint32_t U = S + m * (MATB + 16);  // Xt -> M1
    const uint32_t V = U + BUFB;             // B -> T -> T2

    const uint32_t pU  = U + it * 32;        // mm_rr splat in U
    const uint32_t qU  = U + jq * 32;        // mm_rr pair  in U
    const uint32_t qV  = V + jq * 32;        // pair in V
    const uint32_t ckU = U + it * 1168;      // mm_ck splat rows in U
    const uint32_t tU  = U + it * 1168 + jq * 32;   // own tile in U
    const uint32_t tV  = V + it * 1168 + jq * 32;   // own tile in V
    const uint32_t mV  = V + jq * 1168 + it * 32;   // mirror tile in V
    const uint32_t xU  = U + jq * 1168 + it * 32;   // transposed init rows in U
    const int ond = (it == jq);
    const bool sa = (it <= jq);              // active for symmetric matmuls

    const int tokIdx = blockIdx.x * 2 + m;
    const int tok    = tokens[tokIdx];

    // ---- side-copy loads issued early ----
    float4 breg[8];
    {
        const float4* bsrc = (const float4*)(base_w + (size_t)tok * 512);
        #pragma unroll
        for (int j = 0; j < 8; j++) breg[j] = bsrc[t + 16 * j];
    }
    float cv = 0.0f;
    if (t < 8) cv = conn_w[(size_t)tok * 8 + t];
    float4 gv;
    const bool doGen = blockIdx.x < 64;
    if (doGen) gv = ((const float4*)gen)[blockIdx.x * 32 + lane];

    // ---- load 8x8 fiber tile; store ONLY Xt -> U (free transpose) ----
    {
        const float* fsrc = fiber_w + (size_t)tok * 1024 + 8 * it * 32 + 8 * jq;
        float x[8][8];
        #pragma unroll
        for (int r = 0; r < 8; r++) {
            float4 a = *(const float4*)(fsrc + r * 32);
            float4 b = *(const float4*)(fsrc + r * 32 + 4);
            x[r][0]=a.x; x[r][1]=a.y; x[r][2]=a.z; x[r][3]=a.w;
            x[r][4]=b.x; x[r][5]=b.y; x[r][6]=b.z; x[r][7]=b.w;
        }
        #pragma unroll
        for (int cc = 0; cc < 8; cc++) {
            sts4f(xU + cc * 144,      x[0][cc], x[1][cc], x[2][cc], x[3][cc]);
            sts4f(xU + cc * 144 + 16, x[4][cc], x[5][cc], x[6][cc], x[7][cc]);
        }
    }

    // ---- retire side copies ----
    {
        float4* bdst = (float4*)(out + (size_t)tokIdx * 512);
        #pragma unroll
        for (int j = 0; j < 8; j++) bdst[t + 16 * j] = breg[j];
    }
    if (t < 8) out[OUT_CONN + (size_t)tokIdx * 8 + t] = cv;
    if (doGen) ((float4*)(out + OUT_GEN))[blockIdx.x * 32 + lane] = gv;

    __syncwarp();

    u64 acc[8][4];

    // ===== (1) B = X X^T  (symmetric: lanes it<=jq) =====
    if (sa) {
        zacc(acc);
        mm_rr(pU, qU, acc);
        st_own(tV, acc);                     // V untouched so far: no sync needed
        if (it < jq) st_mirror(mV, acc);
    }
    __syncwarp();

    // ===== (2) S = B*B ; T = 1.875I - 1.25B + 0.375S (symmetric) =====
    u64 bt[8][4];
    if (sa) {
        zacc(acc);
        mm_rr(V + it * 32, qV, acc);
        #pragma unroll
        for (int r = 0; r < 8; r++) {        // reload own B tile before overwrite
            lds2l(tV + r * 144,      bt[r][0], bt[r][1]);
            lds2l(tV + r * 144 + 16, bt[r][2], bt[r][3]);
        }
    }
    __syncwarp();                            // all B reads complete
    if (sa) {
        const u64 CB = pk2(-1.25f, -1.25f);
        const u64 CC = pk2( 0.375f, 0.375f);
        #pragma unroll
        for (int r = 0; r < 8; r++)
            #pragma unroll
            for (int c = 0; c < 4; c++) {
                u64 v = ffma2(bt[r][c], CB, dpair(ond, r, c, 1.875f));
                acc[r][c] = ffma2(acc[r][c], CC, v);
            }
        st_own(tV, acc);                     // T -> V
        if (it < jq) st_mirror(mV, acc);
    }
    __syncwarp();

    // ===== (3) M1 = Xt * T = X^T T = X1^T  (full 16 lanes) =====
    zacc(acc);
    mm_ck(ckU, qV, acc);
    __syncwarp();                            // Xt (U) + T (V) reads complete
    st_own(tU, acc);                         // M1 -> U
    __syncwarp();

    // ===== (4) B2 = M1^T M1 = X1 X1^T ; T2 = 1.5I - 0.5 B2 (symmetric) =====
    if (sa) {
        zacc(acc);
        mm_rr(pU, qU, acc);
        const u64 CH = pk2(-0.5f, -0.5f);
        #pragma unroll
        for (int r = 0; r < 8; r++)
            #pragma unroll
            for (int c = 0; c < 4; c++)
                acc[r][c] = ffma2(acc[r][c], CH, dpair(ond, r, c, 1.5f));
        st_own(tV, acc);                     // T2 -> V (T readers synced at (3))
        if (it < jq) st_mirror(mV, acc);
    }
    __syncwarp();

    // ===== (5) F = M1 * T2 = X1^T T2 = Xf^T ; write Xf (transposed) =====
    zacc(acc);
    mm_ck(ckU, qV, acc);

    {
        float* fdst = out + OUT_FIBER + (size_t)tokIdx * 1024;
        #pragma unroll
        for (int c = 0; c < 4; c++) {
            float lo[8], hi[8];
            #pragma unroll
            for (int r = 0; r < 8; r++) upk2(acc[r][c], lo[r], hi[r]);
            float* r0 = fdst + (8 * jq + 2 * c) * 32 + 8 * it;
            *(float4*)r0       = make_float4(lo[0], lo[1], lo[2], lo[3]);
            *(float4*)(r0 + 4) = make_float4(lo[4], lo[5], lo[6], lo[7]);
            float* r1 = r0 + 32;
            *(float4*)r1       = make_float4(hi[0], hi[1], hi[2], hi[3]);
            *(float4*)(r1 + 4) = make_float4(hi[4], hi[5], hi[6], hi[7]);
        }
    }
}

extern "C" void kernel_launch(void* const* d_in, const int* in_sizes, int n_in,
                              void* d_out, int out_size)
{
    const int*   tokens  = (const int*)  d_in[0];
    const float* base_w  = (const float*)d_in[1];
    const float* fiber_w = (const float*)d_in[2];
    const float* conn_w  = (const float*)d_in[3];
    const float* gen     = (const float*)d_in[4];
    float* out = (float*)d_out;

    static bool configured = false;
    if (!configured) {
        cudaFuncSetAttribute(fiber_bundle_kernel,
                             cudaFuncAttributePreferredSharedMemoryCarveout, 100);
        configured = true;
    }

    dim3 grid(NTOK / 2);   // 16384 one-warp blocks, 2 matrices each
    dim3 block(32);
    fiber_bundle_kernel<<<grid, block>>>(tokens, base_w, fiber_w, conn_w, gen, out);
}

// round 8
// speedup vs baseline: 1.8403x; 1.8403x over previous
#include <cuda_runtime.h>
#include <cstdint>

// ---------------- problem constants ----------------
#define NTOK   32768
#define OUT_FIBER  ((size_t)NTOK * 512)
#define OUT_CONN   (OUT_FIBER + (size_t)NTOK * 1024)
#define OUT_GEN    (OUT_CONN + (size_t)NTOK * 8)

// bf16 plane: 32 rows x 64B data, padded to 80B/row (8-row ldmatrix groups hit
// 8 distinct 16B granules: 80r mod 128 = {0,80,32,112,64,16,96,48}).
#define ROWB   80
#define PLANE  2560
// planes: P1h,P1l (X / X1), P2h,P2l (G / T / T2); lo plane always hi+PLANE.

__device__ __forceinline__ void ldsm4(uint32_t a, uint32_t f[4]) {
    asm volatile("ldmatrix.sync.aligned.m8n8.x4.shared.b16 {%0,%1,%2,%3},[%4];"
                 : "=r"(f[0]), "=r"(f[1]), "=r"(f[2]), "=r"(f[3]) : "r"(a));
}
__device__ __forceinline__ void ldsm4t(uint32_t a, uint32_t f[4]) {
    asm volatile("ldmatrix.sync.aligned.m8n8.x4.trans.shared.b16 {%0,%1,%2,%3},[%4];"
                 : "=r"(f[0]), "=r"(f[1]), "=r"(f[2]), "=r"(f[3]) : "r"(a));
}
__device__ __forceinline__ void mmabf(float d[4], const uint32_t a[4],
                                      uint32_t b0, uint32_t b1) {
    asm volatile("mma.sync.aligned.m16n8k16.row.col.f32.bf16.bf16.f32 "
                 "{%0,%1,%2,%3},{%4,%5,%6,%7},{%8,%9},{%0,%1,%2,%3};"
                 : "+f"(d[0]), "+f"(d[1]), "+f"(d[2]), "+f"(d[3])
                 : "r"(a[0]), "r"(a[1]), "r"(a[2]), "r"(a[3]), "r"(b0), "r"(b1));
}

// split f0,f1 (cols 2c,2c+1) into bf16 hi/lo planes at ahi / ahi+PLANE
__device__ __forceinline__ void split2(uint32_t ahi, float f0, float f1) {
    uint32_t h;
    asm("cvt.rn.bf16x2.f32 %0,%1,%2;" : "=r"(h) : "f"(f1), "f"(f0));
    float h0 = __uint_as_float(h << 16);
    float h1 = __uint_as_float(h & 0xffff0000u);
    uint32_t l;
    asm("cvt.rn.bf16x2.f32 %0,%1,%2;" : "=r"(l) : "f"(f1 - h1), "f"(f0 - h0));
    asm volatile("st.shared.b32 [%0],%1;" :: "r"(ahi), "r"(h));
    asm volatile("st.shared.b32 [%0],%1;" :: "r"(ahi + PLANE), "r"(l));
}
// reconstruct two fp32 values (hi+lo) from planes
__device__ __forceinline__ void load2(uint32_t ahi, float &f0, float &f1) {
    uint32_t h, l;
    asm volatile("ld.shared.b32 %0,[%1];" : "=r"(h) : "r"(ahi));
    asm volatile("ld.shared.b32 %0,[%1];" : "=r"(l) : "r"(ahi + PLANE));
    f0 = __uint_as_float(h << 16)        + __uint_as_float(l << 16);
    f1 = __uint_as_float(h & 0xffff0000u) + __uint_as_float(l & 0xffff0000u);
}

// D[2][4][4] = (ATR ? A^T : A) * B ; A,B are hi-plane bases (lo = +PLANE).
// A row-major in smem; ATR=true computes A^T via trans-ldmatrix tile swap.
// B always consumed col-major via trans-ldmatrix.
template<bool ATR>
__device__ __forceinline__ void mm5(uint32_t A, uint32_t B, float D[2][4][4],
                                    int g1, int g2, int r7)
{
    #pragma unroll
    for (int Kt = 0; Kt < 2; Kt++) {
        uint32_t ah[2][4], al[2][4];
        #pragma unroll
        for (int Mt = 0; Mt < 2; Mt++) {
            if (ATR) {
                uint32_t off = (uint32_t)((Kt * 16 + g2 * 8 + r7) * ROWB + Mt * 32 + g1 * 16);
                ldsm4t(A + off, ah[Mt]);
                ldsm4t(A + PLANE + off, al[Mt]);
            } else {
                uint32_t off = (uint32_t)((Mt * 16 + g1 * 8 + r7) * ROWB + Kt * 32 + g2 * 16);
                ldsm4(A + off, ah[Mt]);
                ldsm4(A + PLANE + off, al[Mt]);
            }
        }
        uint32_t bh[2][4], bl[2][4];
        #pragma unroll
        for (int p = 0; p < 2; p++) {
            uint32_t off = (uint32_t)((Kt * 16 + g1 * 8 + r7) * ROWB + p * 32 + g2 * 16);
            ldsm4t(B + off, bh[p]);
            ldsm4t(B + PLANE + off, bl[p]);
        }
        #pragma unroll
        for (int Mt = 0; Mt < 2; Mt++)
            #pragma unroll
            for (int nt = 0; nt < 4; nt++) {
                const int p = nt >> 1, j = (nt & 1) * 2;
                mmabf(D[Mt][nt], ah[Mt], bh[p][j], bh[p][j + 1]);
                mmabf(D[Mt][nt], ah[Mt], bl[p][j], bl[p][j + 1]);
                mmabf(D[Mt][nt], al[Mt], bh[p][j], bh[p][j + 1]);
                mmabf(D[Mt][nt], al[Mt], bl[p][j], bl[p][j + 1]);
            }
    }
}

__device__ __forceinline__ void zeroD(float D[2][4][4]) {
    #pragma unroll
    for (int m = 0; m < 2; m++)
        #pragma unroll
        for (int n = 0; n < 4; n++)
            #pragma unroll
            for (int k = 0; k < 4; k++) D[m][n][k] = 0.0f;
}

// store D (row-major fp32 tiles) into hi/lo planes at Phi
__device__ __forceinline__ void storeD(uint32_t Phi, float D[2][4][4], int rw, int cp) {
    #pragma unroll
    for (int Mt = 0; Mt < 2; Mt++)
        #pragma unroll
        for (int nt = 0; nt < 4; nt++) {
            uint32_t a = (uint32_t)((Mt * 16 + rw) * ROWB + (nt * 8 + cp) * 2);
            split2(Phi + a,            D[Mt][nt][0], D[Mt][nt][1]);
            split2(Phi + a + 8 * ROWB, D[Mt][nt][2], D[Mt][nt][3]);
        }
}

__global__ __launch_bounds__(32) void fiber_bundle_kernel(
    const int*   __restrict__ tokens,
    const float* __restrict__ base_w,
    const float* __restrict__ fiber_w,
    const float* __restrict__ conn_w,
    const float* __restrict__ gen,
    float*       __restrict__ out)
{
    __shared__ __align__(128) char smraw[4 * PLANE];
    const uint32_t S   = (uint32_t)__cvta_generic_to_shared(smraw);
    const uint32_t P1h = S;                // X -> X1 (hi; lo at +PLANE)
    const uint32_t P2h = S + 2 * PLANE;    // G -> T -> T2

    const int lane = threadIdx.x;
    const int g  = lane >> 3;
    const int g1 = g & 1, g2 = g >> 1;
    const int r7 = lane & 7;
    const int rw = lane >> 2;              // D-frag row within 16
    const int cp = (lane & 3) * 2;         // D-frag col pair base within 8

    const int tokIdx = blockIdx.x;
    const int tok    = tokens[tokIdx];

    // ---- side-copy loads issued early ----
    float4 breg[4];
    {
        const float4* bsrc = (const float4*)(base_w + (size_t)tok * 512);
        #pragma unroll
        for (int j = 0; j < 4; j++) breg[j] = bsrc[lane + 32 * j];
    }
    float cv = 0.0f;
    if (lane < 8) cv = conn_w[(size_t)tok * 8 + lane];
    float4 gv;
    const bool doGen = blockIdx.x < 64;
    if (doGen) gv = ((const float4*)gen)[blockIdx.x * 32 + lane];

    // ---- load X, split into bf16 hi/lo planes ----
    {
        const float4* fsrc = (const float4*)(fiber_w + (size_t)tok * 1024);
        #pragma unroll
        for (int i = 0; i < 8; i++) {
            int idx = i * 32 + lane;               // float4 index in 32x32
            float4 v = fsrc[idx];
            uint32_t a = P1h + (uint32_t)((idx >> 3) * ROWB + (idx & 7) * 8);
            split2(a,     v.x, v.y);
            split2(a + 4, v.z, v.w);
        }
    }

    // ---- retire side copies ----
    {
        float4* bdst = (float4*)(out + (size_t)tokIdx * 512);
        #pragma unroll
        for (int j = 0; j < 4; j++) bdst[lane + 32 * j] = breg[j];
    }
    if (lane < 8) out[OUT_CONN + (size_t)tokIdx * 8 + lane] = cv;
    if (doGen) ((float4*)(out + OUT_GEN))[blockIdx.x * 32 + lane] = gv;

    __syncwarp();

    float D[2][4][4];

    // ===== (1) G = X^T X =====
    zeroD(D);
    mm5<true>(P1h, P1h, D, g1, g2, r7);
    storeD(P2h, D, rw, cp);                       // P2 untouched before this
    __syncwarp();

    // ===== (2) S = G*G ; T = 1.875I - 1.25G + 0.375S =====
    zeroD(D);
    mm5<false>(P2h, P2h, D, g1, g2, r7);
    {
        float gvv[2][4][4];
        #pragma unroll
        for (int Mt = 0; Mt < 2; Mt++)
            #pragma unroll
            for (int nt = 0; nt < 4; nt++) {
                uint32_t a = P2h + (uint32_t)((Mt * 16 + rw) * ROWB + (nt * 8 + cp) * 2);
                load2(a,            gvv[Mt][nt][0], gvv[Mt][nt][1]);
                load2(a + 8 * ROWB, gvv[Mt][nt][2], gvv[Mt][nt][3]);
            }
        __syncwarp();                             // all G reads complete
        #pragma unroll
        for (int Mt = 0; Mt < 2; Mt++)
            #pragma unroll
            for (int nt = 0; nt < 4; nt++) {
                const int c0 = nt * 8 + cp;
                const int r0 = Mt * 16 + rw, r1 = r0 + 8;
                D[Mt][nt][0] = fmaf(D[Mt][nt][0], 0.375f,
                                    fmaf(gvv[Mt][nt][0], -1.25f, (r0 == c0)     ? 1.875f : 0.0f));
                D[Mt][nt][1] = fmaf(D[Mt][nt][1], 0.375f,
                                    fmaf(gvv[Mt][nt][1], -1.25f, (r0 == c0 + 1) ? 1.875f : 0.0f));
                D[Mt][nt][2] = fmaf(D[Mt][nt][2], 0.375f,
                                    fmaf(gvv[Mt][nt][2], -1.25f, (r1 == c0)     ? 1.875f : 0.0f));
                D[Mt][nt][3] = fmaf(D[Mt][nt][3], 0.375f,
                                    fmaf(gvv[Mt][nt][3], -1.25f, (r1 == c0 + 1) ? 1.875f : 0.0f));
            }
        storeD(P2h, D, rw, cp);                   // T -> P2
    }
    __syncwarp();

    // ===== (3) X1 = X * T =====
    zeroD(D);
    mm5<false>(P1h, P2h, D, g1, g2, r7);
    __syncwarp();                                 // X (P1) + T (P2) reads done
    storeD(P1h, D, rw, cp);                       // X1 -> P1
    __syncwarp();

    // ===== (4) G2 = X1^T X1 ; T2 = 1.5I - 0.5 G2 =====
    zeroD(D);
    mm5<true>(P1h, P1h, D, g1, g2, r7);
    #pragma unroll
    for (int Mt = 0; Mt < 2; Mt++)
        #pragma unroll
        for (int nt = 0; nt < 4; nt++) {
            const int c0 = nt * 8 + cp;
            const int r0 = Mt * 16 + rw, r1 = r0 + 8;
            D[Mt][nt][0] = fmaf(D[Mt][nt][0], -0.5f, (r0 == c0)     ? 1.5f : 0.0f);
            D[Mt][nt][1] = fmaf(D[Mt][nt][1], -0.5f, (r0 == c0 + 1) ? 1.5f : 0.0f);
            D[Mt][nt][2] = fmaf(D[Mt][nt][2], -0.5f, (r1 == c0)     ? 1.5f : 0.0f);
            D[Mt][nt][3] = fmaf(D[Mt][nt][3], -0.5f, (r1 == c0 + 1) ? 1.5f : 0.0f);
        }
    storeD(P2h, D, rw, cp);                       // T2 -> P2 (readers synced at (3))
    __syncwarp();

    // ===== (5) Xf = X1 * T2 ; write fp32 result straight to gmem =====
    zeroD(D);
    mm5<false>(P1h, P2h, D, g1, g2, r7);

    {
        float* fdst = out + OUT_FIBER + (size_t)tokIdx * 1024;
        #pragma unroll
        for (int Mt = 0; Mt < 2; Mt++)
            #pragma unroll
            for (int nt = 0; nt < 4; nt++) {
                const int c0 = nt * 8 + cp;
                const int r0 = Mt * 16 + rw;
                *(float2*)(fdst + r0 * 32 + c0)       = make_float2(D[Mt][nt][0], D[Mt][nt][1]);
                *(float2*)(fdst + (r0 + 8) * 32 + c0) = make_float2(D[Mt][nt][2], D[Mt][nt][3]);
            }
    }
}

extern "C" void kernel_launch(void* const* d_in, const int* in_sizes, int n_in,
                              void* d_out, int out_size)
{
    const int*   tokens  = (const int*)  d_in[0];
    const float* base_w  = (const float*)d_in[1];
    const float* fiber_w = (const float*)d_in[2];
    const float* conn_w  = (const float*)d_in[3];
    const float* gen     = (const float*)d_in[4];
    float* out = (float*)d_out;

    static bool configured = false;
    if (!configured) {
        cudaFuncSetAttribute(fiber_bundle_kernel,
                             cudaFuncAttributePreferredSharedMemoryCarveout, 100);
        configured = true;
    }

    dim3 grid(NTOK);       // 32768 one-warp blocks, 1 matrix each
    dim3 block(32);
    fiber_bundle_kernel<<<grid, block>>>(tokens, base_w, fiber_w, conn_w, gen, out);
}

// round 9
// speedup vs baseline: 2.2095x; 1.2007x over previous
#include <cuda_runtime.h>
#include <cstdint>

// ---------------- problem constants ----------------
#define NTOK   32768
#define OUT_FIBER  ((size_t)NTOK * 512)
#define OUT_CONN   (OUT_FIBER + (size_t)NTOK * 1024)
#define OUT_GEN    (OUT_CONN + (size_t)NTOK * 8)

// bf16 plane: 32 rows x 64B data, padded to 80B/row (8-row ldmatrix groups hit
// 8 distinct 16B granules). hi plane at P, lo plane at P+PLANE.
#define ROWB   80
#define PLANE  2560

__device__ __forceinline__ void ldsm4(uint32_t a, uint32_t f[4]) {
    asm volatile("ldmatrix.sync.aligned.m8n8.x4.shared.b16 {%0,%1,%2,%3},[%4];"
                 : "=r"(f[0]), "=r"(f[1]), "=r"(f[2]), "=r"(f[3]) : "r"(a));
}
__device__ __forceinline__ void ldsm4t(uint32_t a, uint32_t f[4]) {
    asm volatile("ldmatrix.sync.aligned.m8n8.x4.trans.shared.b16 {%0,%1,%2,%3},[%4];"
                 : "=r"(f[0]), "=r"(f[1]), "=r"(f[2]), "=r"(f[3]) : "r"(a));
}
__device__ __forceinline__ void stsm4(uint32_t a, uint32_t r0, uint32_t r1,
                                      uint32_t r2, uint32_t r3) {
    asm volatile("stmatrix.sync.aligned.m8n8.x4.shared.b16 [%0],{%1,%2,%3,%4};"
                 :: "r"(a), "r"(r0), "r"(r1), "r"(r2), "r"(r3));
}
__device__ __forceinline__ void mmabf(float d[4], const uint32_t a[4],
                                      uint32_t b0, uint32_t b1) {
    asm volatile("mma.sync.aligned.m16n8k16.row.col.f32.bf16.bf16.f32 "
                 "{%0,%1,%2,%3},{%4,%5,%6,%7},{%8,%9},{%0,%1,%2,%3};"
                 : "+f"(d[0]), "+f"(d[1]), "+f"(d[2]), "+f"(d[3])
                 : "r"(a[0]), "r"(a[1]), "r"(a[2]), "r"(a[3]), "r"(b0), "r"(b1));
}

// pack (even,odd) fp32 -> bf16x2 word (lo half = even)
__device__ __forceinline__ uint32_t cvt2(float even, float odd) {
    uint32_t h; asm("cvt.rn.bf16x2.f32 %0,%1,%2;" : "=r"(h) : "f"(odd), "f"(even));
    return h;
}
// split fp32 pair -> hi/lo bf16x2 planes at ahi / ahi+PLANE (smem)
__device__ __forceinline__ void split2(uint32_t ahi, float f0, float f1) {
    uint32_t h = cvt2(f0, f1);
    float h0 = __uint_as_float(h << 16);
    float h1 = __uint_as_float(h & 0xffff0000u);
    uint32_t l = cvt2(f0 - h0, f1 - h1);
    asm volatile("st.shared.b32 [%0],%1;" :: "r"(ahi), "r"(h));
    asm volatile("st.shared.b32 [%0],%1;" :: "r"(ahi + PLANE), "r"(l));
}

// D (fp32 accum frags) -> bf16x2 hi/lo register packs H/L[Mt][nt][rr]
__device__ __forceinline__ void packHL(const float (&D)[2][4][4],
                                       uint32_t (&H)[2][4][2], uint32_t (&L)[2][4][2]) {
    #pragma unroll
    for (int Mt = 0; Mt < 2; Mt++)
        #pragma unroll
        for (int nt = 0; nt < 4; nt++)
            #pragma unroll
            for (int rr = 0; rr < 2; rr++) {
                float e = D[Mt][nt][2 * rr], o = D[Mt][nt][2 * rr + 1];
                uint32_t h = cvt2(e, o);
                float he = __uint_as_float(h << 16);
                float ho = __uint_as_float(h & 0xffff0000u);
                H[Mt][nt][rr] = h;
                L[Mt][nt][rr] = cvt2(e - he, o - ho);
            }
}

__device__ __forceinline__ void zeroD(float (&D)[2][4][4]) {
    #pragma unroll
    for (int m = 0; m < 2; m++)
        #pragma unroll
        for (int n = 0; n < 4; n++)
            #pragma unroll
            for (int k = 0; k < 4; k++) D[m][n][k] = 0.0f;
}

// ---- Gram: D += M^T M, M in planes at P (3-product hi/lo) ----
__device__ __forceinline__ void gram(uint32_t P, float (&D)[2][4][4],
                                     int g1, int g2, int r7) {
    #pragma unroll
    for (int Kt = 0; Kt < 2; Kt++) {
        uint32_t ah[2][4], al[2][4], bh[2][4], bl[2][4];
        #pragma unroll
        for (int Mt = 0; Mt < 2; Mt++) {
            uint32_t off = (uint32_t)((Kt * 16 + g2 * 8 + r7) * ROWB + Mt * 32 + g1 * 16);
            ldsm4t(P + off, ah[Mt]);
            ldsm4t(P + PLANE + off, al[Mt]);
        }
        #pragma unroll
        for (int p = 0; p < 2; p++) {
            uint32_t off = (uint32_t)((Kt * 16 + g1 * 8 + r7) * ROWB + p * 32 + g2 * 16);
            ldsm4t(P + off, bh[p]);
            ldsm4t(P + PLANE + off, bl[p]);
        }
        #pragma unroll
        for (int Mt = 0; Mt < 2; Mt++)
            #pragma unroll
            for (int nt = 0; nt < 4; nt++) {
                const int p = nt >> 1, j = (nt & 1) * 2;
                mmabf(D[Mt][nt], ah[Mt], bh[p][j], bh[p][j + 1]);
                mmabf(D[Mt][nt], ah[Mt], bl[p][j], bl[p][j + 1]);
                mmabf(D[Mt][nt], al[Mt], bh[p][j], bh[p][j + 1]);
            }
    }
}

// ---- rmul: D += M * T, M in planes at P, T symmetric in reg packs ----
__device__ __forceinline__ void rmul(uint32_t P,
                                     const uint32_t (&TH)[2][4][2],
                                     const uint32_t (&TL)[2][4][2],
                                     float (&D)[2][4][4], int g1, int g2, int r7) {
    #pragma unroll
    for (int Kt = 0; Kt < 2; Kt++) {
        uint32_t ah[2][4], al[2][4];
        #pragma unroll
        for (int Mt = 0; Mt < 2; Mt++) {
            uint32_t off = (uint32_t)((Mt * 16 + g1 * 8 + r7) * ROWB + Kt * 32 + g2 * 16);
            ldsm4(P + off, ah[Mt]);
            ldsm4(P + PLANE + off, al[Mt]);
        }
        #pragma unroll
        for (int Mt = 0; Mt < 2; Mt++)
            #pragma unroll
            for (int nt = 0; nt < 4; nt++) {
                uint32_t b0h = TH[nt >> 1][2 * Kt    ][nt & 1];
                uint32_t b1h = TH[nt >> 1][2 * Kt + 1][nt & 1];
                uint32_t b0l = TL[nt >> 1][2 * Kt    ][nt & 1];
                uint32_t b1l = TL[nt >> 1][2 * Kt + 1][nt & 1];
                mmabf(D[Mt][nt], ah[Mt], b0h, b1h);
                mmabf(D[Mt][nt], ah[Mt], b0l, b1l);
                mmabf(D[Mt][nt], al[Mt], b0h, b1h);
            }
    }
}

// ---- sqsym: S += G * G, G symmetric, entirely from reg packs ----
__device__ __forceinline__ void sqsym(const uint32_t (&GH)[2][4][2],
                                      const uint32_t (&GL)[2][4][2],
                                      float (&S)[2][4][4]) {
    #pragma unroll
    for (int Kt = 0; Kt < 2; Kt++)
        #pragma unroll
        for (int Mt = 0; Mt < 2; Mt++) {
            uint32_t aH[4] = {GH[Mt][2*Kt][0], GH[Mt][2*Kt][1],
                              GH[Mt][2*Kt+1][0], GH[Mt][2*Kt+1][1]};
            uint32_t aL[4] = {GL[Mt][2*Kt][0], GL[Mt][2*Kt][1],
                              GL[Mt][2*Kt+1][0], GL[Mt][2*Kt+1][1]};
            #pragma unroll
            for (int nt = 0; nt < 4; nt++) {
                uint32_t b0h = GH[nt >> 1][2 * Kt    ][nt & 1];
                uint32_t b1h = GH[nt >> 1][2 * Kt + 1][nt & 1];
                uint32_t b0l = GL[nt >> 1][2 * Kt    ][nt & 1];
                uint32_t b1l = GL[nt >> 1][2 * Kt + 1][nt & 1];
                mmabf(S[Mt][nt], aH, b0h, b1h);
                mmabf(S[Mt][nt], aH, b0l, b1l);
                mmabf(S[Mt][nt], aL, b0h, b1h);
            }
        }
}

__global__ __launch_bounds__(32) void fiber_bundle_kernel(
    const int*   __restrict__ tokens,
    const float* __restrict__ base_w,
    const float* __restrict__ fiber_w,
    const float* __restrict__ conn_w,
    const float* __restrict__ gen,
    float*       __restrict__ out)
{
    __shared__ __align__(128) char smraw[2 * PLANE];
    const uint32_t P1h = (uint32_t)__cvta_generic_to_shared(smraw);   // X -> X1

    const int lane = threadIdx.x;
    const int g  = lane >> 3;
    const int g1 = g & 1, g2 = g >> 1;
    const int r7 = lane & 7;
    const int rw = lane >> 2;
    const int cp = (lane & 3) * 2;

    const int tokIdx = blockIdx.x;
    const int tok    = tokens[tokIdx];

    // ---- side-copy loads issued early ----
    float4 breg[4];
    {
        const float4* bsrc = (const float4*)(base_w + (size_t)tok * 512);
        #pragma unroll
        for (int j = 0; j < 4; j++) breg[j] = bsrc[lane + 32 * j];
    }
    float cv = 0.0f;
    if (lane < 8) cv = conn_w[(size_t)tok * 8 + lane];
    float4 gv;
    const bool doGen = blockIdx.x < 64;
    if (doGen) gv = ((const float4*)gen)[blockIdx.x * 32 + lane];

    // ---- load X, split into bf16 hi/lo planes ----
    {
        const float4* fsrc = (const float4*)(fiber_w + (size_t)tok * 1024);
        #pragma unroll
        for (int i = 0; i < 8; i++) {
            int idx = i * 32 + lane;
            float4 v = fsrc[idx];
            uint32_t a = P1h + (uint32_t)((idx >> 3) * ROWB + (idx & 7) * 8);
            split2(a,     v.x, v.y);
            split2(a + 4, v.z, v.w);
        }
    }

    // ---- retire side copies ----
    {
        float4* bdst = (float4*)(out + (size_t)tokIdx * 512);
        #pragma unroll
        for (int j = 0; j < 4; j++) bdst[lane + 32 * j] = breg[j];
    }
    if (lane < 8) out[OUT_CONN + (size_t)tokIdx * 8 + lane] = cv;
    if (doGen) ((float4*)(out + OUT_GEN))[blockIdx.x * 32 + lane] = gv;

    __syncwarp();

    float D[2][4][4];
    uint32_t H[2][4][2], L[2][4][2];

    // ===== (1) G = X^T X =====
    zeroD(D);
    gram(P1h, D, g1, g2, r7);

    // ===== (2) S = G*G (regs only); T = 1.875I - 1.25G + 0.375S =====
    packHL(D, H, L);                       // G packs
    {
        float S[2][4][4];
        zeroD(S);
        sqsym(H, L, S);
        #pragma unroll
        for (int Mt = 0; Mt < 2; Mt++)
            #pragma unroll
            for (int nt = 0; nt < 4; nt++) {
                const int c0 = nt * 8 + cp;
                const int r0 = Mt * 16 + rw, r1 = r0 + 8;
                D[Mt][nt][0] = fmaf(S[Mt][nt][0], 0.375f,
                                    fmaf(D[Mt][nt][0], -1.25f, (r0 == c0)     ? 1.875f : 0.0f));
                D[Mt][nt][1] = fmaf(S[Mt][nt][1], 0.375f,
                                    fmaf(D[Mt][nt][1], -1.25f, (r0 == c0 + 1) ? 1.875f : 0.0f));
                D[Mt][nt][2] = fmaf(S[Mt][nt][2], 0.375f,
                                    fmaf(D[Mt][nt][2], -1.25f, (r1 == c0)     ? 1.875f : 0.0f));
                D[Mt][nt][3] = fmaf(S[Mt][nt][3], 0.375f,
                                    fmaf(D[Mt][nt][3], -1.25f, (r1 == c0 + 1) ? 1.875f : 0.0f));
            }
    }
    packHL(D, H, L);                       // T packs (B operand from regs)

    // ===== (3) X1 = X * T =====
    zeroD(D);
    rmul(P1h, H, L, D, g1, g2, r7);
    packHL(D, H, L);                       // X1 packs
    __syncwarp();                          // X reads done before overwrite
    #pragma unroll
    for (int r = 0; r < 4; r++) {          // X1 -> planes via stmatrix
        uint32_t a = P1h + (uint32_t)((8 * r + r7) * ROWB + g * 16);
        stsm4(a,         H[r >> 1][0][r & 1], H[r >> 1][1][r & 1],
                         H[r >> 1][2][r & 1], H[r >> 1][3][r & 1]);
        stsm4(a + PLANE, L[r >> 1][0][r & 1], L[r >> 1][1][r & 1],
                         L[r >> 1][2][r & 1], L[r >> 1][3][r & 1]);
    }
    __syncwarp();

    // ===== (4) G2 = X1^T X1 ; T2 = 1.5I - 0.5 G2 =====
    zeroD(D);
    gram(P1h, D, g1, g2, r7);
    #pragma unroll
    for (int Mt = 0; Mt < 2; Mt++)
        #pragma unroll
        for (int nt = 0; nt < 4; nt++) {
            const int c0 = nt * 8 + cp;
            const int r0 = Mt * 16 + rw, r1 = r0 + 8;
            D[Mt][nt][0] = fmaf(D[Mt][nt][0], -0.5f, (r0 == c0)     ? 1.5f : 0.0f);
            D[Mt][nt][1] = fmaf(D[Mt][nt][1], -0.5f, (r0 == c0 + 1) ? 1.5f : 0.0f);
            D[Mt][nt][2] = fmaf(D[Mt][nt][2], -0.5f, (r1 == c0)     ? 1.5f : 0.0f);
            D[Mt][nt][3] = fmaf(D[Mt][nt][3], -0.5f, (r1 == c0 + 1) ? 1.5f : 0.0f);
        }
    packHL(D, H, L);                       // T2 packs

    // ===== (5) Xf = X1 * T2 -> gmem =====
    zeroD(D);
    rmul(P1h, H, L, D, g1, g2, r7);

    {
        float* fdst = out + OUT_FIBER + (size_t)tokIdx * 1024;
        #pragma unroll
        for (int Mt = 0; Mt < 2; Mt++)
            #pragma unroll
            for (int nt = 0; nt < 4; nt++) {
                const int c0 = nt * 8 + cp;
                const int r0 = Mt * 16 + rw;
                *(float2*)(fdst + r0 * 32 + c0)       = make_float2(D[Mt][nt][0], D[Mt][nt][1]);
                *(float2*)(fdst + (r0 + 8) * 32 + c0) = make_float2(D[Mt][nt][2], D[Mt][nt][3]);
            }
    }
}

extern "C" void kernel_launch(void* const* d_in, const int* in_sizes, int n_in,
                              void* d_out, int out_size)
{
    const int*   tokens  = (const int*)  d_in[0];
    const float* base_w  = (const float*)d_in[1];
    const float* fiber_w = (const float*)d_in[2];
    const float* conn_w  = (const float*)d_in[3];
    const float* gen     = (const float*)d_in[4];
    float* out = (float*)d_out;

    static bool configured = false;
    if (!configured) {
        cudaFuncSetAttribute(fiber_bundle_kernel,
                             cudaFuncAttributePreferredSharedMemoryCarveout, 100);
        configured = true;
    }

    dim3 grid(NTOK);       // 32768 one-warp blocks, 1 matrix each
    dim3 block(32);
    fiber_bundle_kernel<<<grid, block>>>(tokens, base_w, fiber_w, conn_w, gen, out);
}

// round 10
// speedup vs baseline: 2.2737x; 1.0291x over previous
#include <cuda_runtime.h>
#include <cstdint>

// ---------------- problem constants ----------------
#define NTOK   32768
#define OUT_FIBER  ((size_t)NTOK * 512)
#define OUT_CONN   (OUT_FIBER + (size_t)NTOK * 1024)
#define OUT_GEN    (OUT_CONN + (size_t)NTOK * 8)

// bf16 plane: 32 rows x 64B data, padded to 80B/row (8-row ldmatrix groups hit
// 8 distinct 16B granules). hi plane at P, lo plane at P+PLANE.
#define ROWB   80
#define PLANE  2560

__device__ __forceinline__ void ldsm4(uint32_t a, uint32_t f[4]) {
    asm volatile("ldmatrix.sync.aligned.m8n8.x4.shared.b16 {%0,%1,%2,%3},[%4];"
                 : "=r"(f[0]), "=r"(f[1]), "=r"(f[2]), "=r"(f[3]) : "r"(a));
}
__device__ __forceinline__ void ldsm4t(uint32_t a, uint32_t f[4]) {
    asm volatile("ldmatrix.sync.aligned.m8n8.x4.trans.shared.b16 {%0,%1,%2,%3},[%4];"
                 : "=r"(f[0]), "=r"(f[1]), "=r"(f[2]), "=r"(f[3]) : "r"(a));
}
__device__ __forceinline__ void stsm4(uint32_t a, uint32_t r0, uint32_t r1,
                                      uint32_t r2, uint32_t r3) {
    asm volatile("stmatrix.sync.aligned.m8n8.x4.shared.b16 [%0],{%1,%2,%3,%4};"
                 :: "r"(a), "r"(r0), "r"(r1), "r"(r2), "r"(r3));
}
__device__ __forceinline__ void mmabf(float d[4], const uint32_t a[4],
                                      uint32_t b0, uint32_t b1) {
    asm volatile("mma.sync.aligned.m16n8k16.row.col.f32.bf16.bf16.f32 "
                 "{%0,%1,%2,%3},{%4,%5,%6,%7},{%8,%9},{%0,%1,%2,%3};"
                 : "+f"(d[0]), "+f"(d[1]), "+f"(d[2]), "+f"(d[3])
                 : "r"(a[0]), "r"(a[1]), "r"(a[2]), "r"(a[3]), "r"(b0), "r"(b1));
}

// pack (even,odd) fp32 -> bf16x2 word (lo half = even)
__device__ __forceinline__ uint32_t cvt2(float even, float odd) {
    uint32_t h; asm("cvt.rn.bf16x2.f32 %0,%1,%2;" : "=r"(h) : "f"(odd), "f"(even));
    return h;
}
__device__ __forceinline__ uint32_t lores(uint32_t h, float e, float o) {
    float he = __uint_as_float(h << 16);
    float ho = __uint_as_float(h & 0xffff0000u);
    return cvt2(e - he, o - ho);
}
__device__ __forceinline__ void sts4u(uint32_t a, uint32_t x, uint32_t y,
                                      uint32_t z, uint32_t w) {
    asm volatile("st.shared.v4.b32 [%0],{%1,%2,%3,%4};"
                 :: "r"(a), "r"(x), "r"(y), "r"(z), "r"(w));
}

// D (fp32 accum frags) -> bf16x2 hi/lo register packs H/L[Mt][nt][rr]
__device__ __forceinline__ void packHL(const float (&D)[2][4][4],
                                       uint32_t (&H)[2][4][2], uint32_t (&L)[2][4][2]) {
    #pragma unroll
    for (int Mt = 0; Mt < 2; Mt++)
        #pragma unroll
        for (int nt = 0; nt < 4; nt++)
            #pragma unroll
            for (int rr = 0; rr < 2; rr++) {
                float e = D[Mt][nt][2 * rr], o = D[Mt][nt][2 * rr + 1];
                uint32_t h = cvt2(e, o);
                H[Mt][nt][rr] = h;
                L[Mt][nt][rr] = lores(h, e, o);
            }
}

__device__ __forceinline__ void zeroD(float (&D)[2][4][4]) {
    #pragma unroll
    for (int m = 0; m < 2; m++)
        #pragma unroll
        for (int n = 0; n < 4; n++)
            #pragma unroll
            for (int k = 0; k < 4; k++) D[m][n][k] = 0.0f;
}

// ---- Gram: D += M^T M, M in planes at P (3-product hi/lo) ----
__device__ __forceinline__ void gram(uint32_t P, float (&D)[2][4][4],
                                     int g1, int g2, int r7) {
    #pragma unroll
    for (int Kt = 0; Kt < 2; Kt++) {
        uint32_t ah[2][4], al[2][4], bh[2][4], bl[2][4];
        #pragma unroll
        for (int Mt = 0; Mt < 2; Mt++) {
            uint32_t off = (uint32_t)((Kt * 16 + g2 * 8 + r7) * ROWB + Mt * 32 + g1 * 16);
            ldsm4t(P + off, ah[Mt]);
            ldsm4t(P + PLANE + off, al[Mt]);
        }
        #pragma unroll
        for (int p = 0; p < 2; p++) {
            uint32_t off = (uint32_t)((Kt * 16 + g1 * 8 + r7) * ROWB + p * 32 + g2 * 16);
            ldsm4t(P + off, bh[p]);
            ldsm4t(P + PLANE + off, bl[p]);
        }
        #pragma unroll
        for (int Mt = 0; Mt < 2; Mt++)
            #pragma unroll
            for (int nt = 0; nt < 4; nt++) {
                const int p = nt >> 1, j = (nt & 1) * 2;
                mmabf(D[Mt][nt], ah[Mt], bh[p][j], bh[p][j + 1]);
                mmabf(D[Mt][nt], ah[Mt], bl[p][j], bl[p][j + 1]);
                mmabf(D[Mt][nt], al[Mt], bh[p][j], bh[p][j + 1]);
            }
    }
}

// ---- rmul: D += M * T, M in planes at P, T symmetric in reg packs ----
__device__ __forceinline__ void rmul(uint32_t P,
                                     const uint32_t (&TH)[2][4][2],
                                     const uint32_t (&TL)[2][4][2],
                                     float (&D)[2][4][4], int g1, int g2, int r7) {
    #pragma unroll
    for (int Kt = 0; Kt < 2; Kt++) {
        uint32_t ah[2][4], al[2][4];
        #pragma unroll
        for (int Mt = 0; Mt < 2; Mt++) {
            uint32_t off = (uint32_t)((Mt * 16 + g1 * 8 + r7) * ROWB + Kt * 32 + g2 * 16);
            ldsm4(P + off, ah[Mt]);
            ldsm4(P + PLANE + off, al[Mt]);
        }
        #pragma unroll
        for (int Mt = 0; Mt < 2; Mt++)
            #pragma unroll
            for (int nt = 0; nt < 4; nt++) {
                uint32_t b0h = TH[nt >> 1][2 * Kt    ][nt & 1];
                uint32_t b1h = TH[nt >> 1][2 * Kt + 1][nt & 1];
                uint32_t b0l = TL[nt >> 1][2 * Kt    ][nt & 1];
                uint32_t b1l = TL[nt >> 1][2 * Kt + 1][nt & 1];
                mmabf(D[Mt][nt], ah[Mt], b0h, b1h);
                mmabf(D[Mt][nt], ah[Mt], b0l, b1l);
                mmabf(D[Mt][nt], al[Mt], b0h, b1h);
            }
    }
}

// ---- sqsym: D += G * G, G symmetric, entirely from reg packs ----
__device__ __forceinline__ void sqsym(const uint32_t (&GH)[2][4][2],
                                      const uint32_t (&GL)[2][4][2],
                                      float (&D)[2][4][4]) {
    #pragma unroll
    for (int Kt = 0; Kt < 2; Kt++)
        #pragma unroll
        for (int Mt = 0; Mt < 2; Mt++) {
            uint32_t aH[4] = {GH[Mt][2*Kt][0], GH[Mt][2*Kt][1],
                              GH[Mt][2*Kt+1][0], GH[Mt][2*Kt+1][1]};
            uint32_t aL[4] = {GL[Mt][2*Kt][0], GL[Mt][2*Kt][1],
                              GL[Mt][2*Kt+1][0], GL[Mt][2*Kt+1][1]};
            #pragma unroll
            for (int nt = 0; nt < 4; nt++) {
                uint32_t b0h = GH[nt >> 1][2 * Kt    ][nt & 1];
                uint32_t b1h = GH[nt >> 1][2 * Kt + 1][nt & 1];
                uint32_t b0l = GL[nt >> 1][2 * Kt    ][nt & 1];
                uint32_t b1l = GL[nt >> 1][2 * Kt + 1][nt & 1];
                mmabf(D[Mt][nt], aH, b0h, b1h);
                mmabf(D[Mt][nt], aH, b0l, b1l);
                mmabf(D[Mt][nt], aL, b0h, b1h);
            }
        }
}

__global__ __launch_bounds__(32, 16) void fiber_bundle_kernel(
    const int*   __restrict__ tokens,
    const float* __restrict__ base_w,
    const float* __restrict__ fiber_w,
    const float* __restrict__ conn_w,
    const float* __restrict__ gen,
    float*       __restrict__ out)
{
    __shared__ __align__(128) char smraw[2 * PLANE];
    const uint32_t P1h = (uint32_t)__cvta_generic_to_shared(smraw);   // X -> X1

    const int lane = threadIdx.x;
    const int g  = lane >> 3;
    const int g1 = g & 1, g2 = g >> 1;
    const int r7 = lane & 7;
    const int rw = lane >> 2;
    const int cp = (lane & 3) * 2;

    const int tokIdx = blockIdx.x;
    const int tok    = tokens[tokIdx];

    // ---- side-copy loads issued early ----
    float4 breg[4];
    {
        const float4* bsrc = (const float4*)(base_w + (size_t)tok * 512);
        #pragma unroll
        for (int j = 0; j < 4; j++) breg[j] = bsrc[lane + 32 * j];
    }
    float cv = 0.0f;
    if (lane < 8) cv = conn_w[(size_t)tok * 8 + lane];
    float4 gv;
    const bool doGen = blockIdx.x < 64;
    if (doGen) gv = ((const float4*)gen)[blockIdx.x * 32 + lane];

    // ---- load X (8 row-contiguous floats per lane-iter), split to hi/lo planes ----
    {
        const float4* fsrc = (const float4*)(fiber_w + (size_t)tok * 1024);
        #pragma unroll
        for (int i = 0; i < 4; i++) {
            int p = i * 32 + lane;                 // 8-float chunk index 0..127
            float4 v0 = fsrc[2 * p];
            float4 v1 = fsrc[2 * p + 1];
            int row = p >> 2, c8 = (p & 3) * 8;
            uint32_t a = P1h + (uint32_t)(row * ROWB + c8 * 2);
            uint32_t h0 = cvt2(v0.x, v0.y), h1 = cvt2(v0.z, v0.w);
            uint32_t h2 = cvt2(v1.x, v1.y), h3 = cvt2(v1.z, v1.w);
            sts4u(a, h0, h1, h2, h3);
            sts4u(a + PLANE, lores(h0, v0.x, v0.y), lores(h1, v0.z, v0.w),
                             lores(h2, v1.x, v1.y), lores(h3, v1.z, v1.w));
        }
    }

    // ---- retire side copies ----
    {
        float4* bdst = (float4*)(out + (size_t)tokIdx * 512);
        #pragma unroll
        for (int j = 0; j < 4; j++) bdst[lane + 32 * j] = breg[j];
    }
    if (lane < 8) out[OUT_CONN + (size_t)tokIdx * 8 + lane] = cv;
    if (doGen) ((float4*)(out + OUT_GEN))[blockIdx.x * 32 + lane] = gv;

    __syncwarp();

    float D[2][4][4];
    uint32_t H[2][4][2], L[2][4][2];

    // ===== (1) G = X^T X =====
    zeroD(D);
    gram(P1h, D, g1, g2, r7);

    // ===== (2) T = 0.375*(G*G + 5I - (10/3)G)  (regs only) =====
    packHL(D, H, L);                       // G packs
    #pragma unroll
    for (int Mt = 0; Mt < 2; Mt++)
        #pragma unroll
        for (int nt = 0; nt < 4; nt++) {
            const int c0 = nt * 8 + cp;
            const int r0 = Mt * 16 + rw, r1 = r0 + 8;
            D[Mt][nt][0] = fmaf(D[Mt][nt][0], -3.33333333f, (r0 == c0)     ? 5.0f : 0.0f);
            D[Mt][nt][1] = fmaf(D[Mt][nt][1], -3.33333333f, (r0 == c0 + 1) ? 5.0f : 0.0f);
            D[Mt][nt][2] = fmaf(D[Mt][nt][2], -3.33333333f, (r1 == c0)     ? 5.0f : 0.0f);
            D[Mt][nt][3] = fmaf(D[Mt][nt][3], -3.33333333f, (r1 == c0 + 1) ? 5.0f : 0.0f);
        }
    sqsym(H, L, D);                        // D = G^2 + 5I - (10/3)G
    #pragma unroll
    for (int Mt = 0; Mt < 2; Mt++)
        #pragma unroll
        for (int nt = 0; nt < 4; nt++)
            #pragma unroll
            for (int k = 0; k < 4; k++) D[Mt][nt][k] *= 0.375f;
    packHL(D, H, L);                       // T packs

    // ===== (3) X1 = X * T =====
    zeroD(D);
    rmul(P1h, H, L, D, g1, g2, r7);
    packHL(D, H, L);                       // X1 packs
    __syncwarp();                          // X reads done before overwrite
    #pragma unroll
    for (int r = 0; r < 4; r++) {          // X1 -> planes via stmatrix
        uint32_t a = P1h + (uint32_t)((8 * r + r7) * ROWB + g * 16);
        stsm4(a,         H[r >> 1][0][r & 1], H[r >> 1][1][r & 1],
                         H[r >> 1][2][r & 1], H[r >> 1][3][r & 1]);
        stsm4(a + PLANE, L[r >> 1][0][r & 1], L[r >> 1][1][r & 1],
                         L[r >> 1][2][r & 1], L[r >> 1][3][r & 1]);
    }
    __syncwarp();

    // ===== (4) G2 = X1^T X1 ; T2 = 1.5I - 0.5 G2 =====
    zeroD(D);
    gram(P1h, D, g1, g2, r7);
    #pragma unroll
    for (int Mt = 0; Mt < 2; Mt++)
        #pragma unroll
        for (int nt = 0; nt < 4; nt++) {
            const int c0 = nt * 8 + cp;
            const int r0 = Mt * 16 + rw, r1 = r0 + 8;
            D[Mt][nt][0] = fmaf(D[Mt][nt][0], -0.5f, (r0 == c0)     ? 1.5f : 0.0f);
            D[Mt][nt][1] = fmaf(D[Mt][nt][1], -0.5f, (r0 == c0 + 1) ? 1.5f : 0.0f);
            D[Mt][nt][2] = fmaf(D[Mt][nt][2], -0.5f, (r1 == c0)     ? 1.5f : 0.0f);
            D[Mt][nt][3] = fmaf(D[Mt][nt][3], -0.5f, (r1 == c0 + 1) ? 1.5f : 0.0f);
        }
    packHL(D, H, L);                       // T2 packs

    // ===== (5) Xf = X1 * T2 -> gmem =====
    zeroD(D);
    rmul(P1h, H, L, D, g1, g2, r7);

    {
        float* fdst = out + OUT_FIBER + (size_t)tokIdx * 1024;
        #pragma unroll
        for (int Mt = 0; Mt < 2; Mt++)
            #pragma unroll
            for (int nt = 0; nt < 4; nt++) {
                const int c0 = nt * 8 + cp;
                const int r0 = Mt * 16 + rw;
                *(float2*)(fdst + r0 * 32 + c0)       = make_float2(D[Mt][nt][0], D[Mt][nt][1]);
                *(float2*)(fdst + (r0 + 8) * 32 + c0) = make_float2(D[Mt][nt][2], D[Mt][nt][3]);
            }
    }
}

extern "C" void kernel_launch(void* const* d_in, const int* in_sizes, int n_in,
                              void* d_out, int out_size)
{
    const int*   tokens  = (const int*)  d_in[0];
    const float* base_w  = (const float*)d_in[1];
    const float* fiber_w = (const float*)d_in[2];
    const float* conn_w  = (const float*)d_in[3];
    const float* gen     = (const float*)d_in[4];
    float* out = (float*)d_out;

    static bool configured = false;
    if (!configured) {
        cudaFuncSetAttribute(fiber_bundle_kernel,
                             cudaFuncAttributePreferredSharedMemoryCarveout, 100);
        configured = true;
    }

    dim3 grid(NTOK);       // 32768 one-warp blocks, 1 matrix each
    dim3 block(32);
    fiber_bundle_kernel<<<grid, block>>>(tokens, base_w, fiber_w, conn_w, gen, out);
}